// round 17
// baseline (speedup 1.0000x reference)
#include <cuda_runtime.h>
#include <cuda_bf16.h>
#include <cstdint>

#define NB      16384
#define ADIM    32
#define KTOT    2048
#define EDIM    128
#define NACT    1000
#define ODIM    64

#define KC      32                 // K per chunk (bf16 elems)
#define NCHUNK  (KTOT / KC)        // 64
#define PITCH   40                 // bf16 per smem row (80B) -> conflict-free ldmatrix
#define TILE_T  (64 * PITCH * 2)   // 5120 B per 64-row tile
#define BUF_B   (4 * TILE_T)       // Ah Al Bh Bl = 20480
#define DSMEM   (2 * BUF_B)        // 40960 (double buffer)
#define ATT_STRIDE 68              // floats; conflict-free epilogue staging

#define PW_BLOCKS 256
#define P2_BLOCKS 63

// ---------------- scratch ----------------
__device__ float g_s_table[NACT];
__device__ float g_T2[NACT * ODIM];
__device__ float g_bias[ODIM];
__device__ __nv_bfloat16 g_Wt_h[ODIM * KTOT];   // Wfused^T hi, [o][k]
__device__ __nv_bfloat16 g_Wt_l[ODIM * KTOT];   // Wfused^T lo

// ---------------- helpers ----------------
__device__ __forceinline__ uint32_t smem_u32(const void* p) {
    uint32_t a;
    asm("{ .reg .u64 t; cvta.to.shared.u64 t, %1; cvt.u32.u64 %0, t; }"
        : "=r"(a) : "l"(p));
    return a;
}
__device__ __forceinline__ void ldsm_x4(uint32_t* r, uint32_t addr) {
    asm volatile("ldmatrix.sync.aligned.m8n8.x4.shared.b16 {%0,%1,%2,%3}, [%4];"
                 : "=r"(r[0]), "=r"(r[1]), "=r"(r[2]), "=r"(r[3]) : "r"(addr));
}
__device__ __forceinline__ void mma_bf16(float* c, const uint32_t* a, const uint32_t* b) {
    asm volatile(
        "mma.sync.aligned.m16n8k16.row.col.f32.bf16.bf16.f32 "
        "{%0,%1,%2,%3}, {%4,%5,%6,%7}, {%8,%9}, {%0,%1,%2,%3};"
        : "+f"(c[0]), "+f"(c[1]), "+f"(c[2]), "+f"(c[3])
        : "r"(a[0]), "r"(a[1]), "r"(a[2]), "r"(a[3]), "r"(b[0]), "r"(b[1]));
}
__device__ __forceinline__ void split2(float x, float y, uint32_t& hi, uint32_t& lo) {
    __nv_bfloat162 h = __floats2bfloat162_rn(x, y);
    __nv_bfloat162 l = __floats2bfloat162_rn(x - __low2float(h), y - __high2float(h));
    hi = *reinterpret_cast<uint32_t*>(&h);
    lo = *reinterpret_cast<uint32_t*>(&l);
}

// ---------------------------------------------------------------------------
// prep_all (unchanged from R15/R16): merged prep_w + prep2, shared smem arena.
// ---------------------------------------------------------------------------
#define PREP_SMEM 41472
__global__ void __launch_bounds__(256) prep_all_kernel(
    const float* __restrict__ W_state, const float* __restrict__ W_out,
    const float* __restrict__ b_state, const float* __restrict__ b_out,
    const float* __restrict__ table,   const float* __restrict__ W_att,
    const float* __restrict__ b_att)
{
    __shared__ __align__(16) char smbuf[PREP_SMEM];
    const int tid = threadIdx.x;

    if (blockIdx.x < PW_BLOCKS) {
        float* W1s = (float*)smbuf;
        float (*Ast)[EDIM] = (float(*)[EDIM])(smbuf + EDIM * ODIM * 4);

        const int k0 = blockIdx.x * 8;
        #pragma unroll
        for (int i = 0; i < 32; i++)
            W1s[tid + i * 256] = W_out[tid + i * 256];
        for (int idx = tid; idx < 8 * EDIM; idx += 256) {
            const int r = idx >> 7, e = idx & 127;
            Ast[r][e] = W_state[(size_t)(k0 + r) * EDIM + e];
        }
        __syncthreads();

        const int o  = tid & 63;
        const int kk = tid >> 6;
        float a0 = 0.f, a1 = 0.f;
        #pragma unroll 8
        for (int e = 0; e < EDIM; e++) {
            const float w1 = W1s[e * ODIM + o];
            a0 = fmaf(Ast[kk * 2][e],     w1, a0);
            a1 = fmaf(Ast[kk * 2 + 1][e], w1, a1);
        }
        uint32_t hh, ll;
        split2(a0, a1, hh, ll);
        const size_t base = (size_t)o * KTOT + k0 + kk * 2;
        *(uint32_t*)&g_Wt_h[base] = hh;
        *(uint32_t*)&g_Wt_l[base] = ll;

        if (blockIdx.x == 0 && tid < ODIM) {
            float b = b_out[tid];
            #pragma unroll 8
            for (int e = 0; e < EDIM; e++)
                b = fmaf(b_state[e], W1s[e * ODIM + tid], b);
            g_bias[tid] = b;
        }
    } else {
        float* Wo2 = (float*)smbuf;
        float (*rows)[EDIM] = (float(*)[EDIM])(smbuf + EDIM * ODIM * 4);
        float* watt = (float*)(smbuf + EDIM * ODIM * 4 + 16 * EDIM * 4);

        const int r0 = (blockIdx.x - PW_BLOCKS) * 16;
        #pragma unroll
        for (int i = 0; i < 32; i++)
            Wo2[tid + i * 256] = W_out[EDIM * ODIM + tid + i * 256];
        if (tid < EDIM) watt[tid] = W_att[tid];
        for (int idx = tid; idx < 16 * EDIM; idx += 256) {
            const int r = idx >> 7, e = idx & 127;
            rows[r][e] = (r0 + r < NACT) ? table[(size_t)(r0 + r) * EDIM + e] : 0.f;
        }
        __syncthreads();

        if (tid < 16 && r0 + tid < NACT) {
            float s = 0.f;
            #pragma unroll 8
            for (int e = 0; e < EDIM; e++) s = fmaf(rows[tid][e], watt[e], s);
            g_s_table[r0 + tid] = s + b_att[0];
        }

        #pragma unroll
        for (int i = 0; i < 4; i++) {
            const int idx = tid + i * 256;
            const int r = idx >> 6, o = idx & 63;
            if (r0 + r < NACT) {
                float acc = 0.f;
                #pragma unroll 8
                for (int e = 0; e < EDIM; e++)
                    acc = fmaf(rows[r][e], Wo2[e * ODIM + o], acc);
                g_T2[(size_t)(r0 + r) * ODIM + o] = acc;
            }
        }
    }
}

// ---------------------------------------------------------------------------
// gemm_fused: R15 structure + DISTANCE-2 register prefetch (LDG for chunk c+2
// issued at top of chunk c; STS of chunk c+1 at bottom -> ~2 compute blocks of
// latency cover instead of 1). Loop unrolled x2 for static reg-buffer indices.
// ---------------------------------------------------------------------------
__global__ void __launch_bounds__(256, 2)
gemm_fused_kernel(const float* __restrict__ state,
                  const int* __restrict__ action,
                  float* __restrict__ out)
{
    extern __shared__ __align__(128) char dsm[];
    const uint32_t dyn = smem_u32(dsm);

    const int tid = threadIdx.x;
    const int wid = tid >> 5, lane = tid & 31;
    const int warp_m = wid & 1;
    const int warp_n = wid >> 1;
    const int rowBase = blockIdx.x * 64;

    const int frow = tid >> 2;
    const int fseg = (tid & 3) * 8;
    const float* asrc = state + (size_t)(rowBase + frow) * KTOT + fseg;
    const __nv_bfloat16* bh_src = g_Wt_h + (size_t)frow * KTOT + fseg;
    const __nv_bfloat16* bl_src = g_Wt_l + (size_t)frow * KTOT + fseg;
    const uint32_t foff = frow * (PITCH * 2) + fseg * 2;

    const int lg = lane >> 3, lr = lane & 7;

    float acc[2][2][4];
    #pragma unroll
    for (int mi = 0; mi < 2; mi++)
        #pragma unroll
        for (int j = 0; j < 2; j++)
            #pragma unroll
            for (int q = 0; q < 4; q++) acc[mi][j][q] = 0.f;

    // two register staging buffers
    float4 a0_0, a1_0, a0_1, a1_1;
    uint4  bh_0, bl_0, bh_1, bl_1;

    // compute block over one smem buffer
    auto compute = [&](uint32_t sb) {
        const uint32_t sAh = sb, sAl = sb + TILE_T;
        const uint32_t sBh = sb + 2 * TILE_T, sBl = sb + 3 * TILE_T;
        #pragma unroll
        for (int s = 0; s < 2; s++) {
            uint32_t ah[2][4], al[2][4], bb[4];
            #pragma unroll
            for (int mi = 0; mi < 2; mi++) {
                const int arow = warp_m * 32 + mi * 16 + (lg & 1) * 8 + lr;
                const int acol = s * 16 + (lg >> 1) * 8;
                const uint32_t off = arow * (PITCH * 2) + acol * 2;
                ldsm_x4(ah[mi], sAh + off);
                ldsm_x4(al[mi], sAl + off);
            }
            const int nrow = warp_n * 16 + (lg >> 1) * 8 + lr;
            const int ncol = s * 16 + (lg & 1) * 8;
            ldsm_x4(bb, sBh + nrow * (PITCH * 2) + ncol * 2);
            #pragma unroll
            for (int mi = 0; mi < 2; mi++)
                #pragma unroll
                for (int j = 0; j < 2; j++)
                    mma_bf16(acc[mi][j], ah[mi], &bb[j * 2]);
            #pragma unroll
            for (int mi = 0; mi < 2; mi++)
                #pragma unroll
                for (int j = 0; j < 2; j++)
                    mma_bf16(acc[mi][j], al[mi], &bb[j * 2]);
            ldsm_x4(bb, sBl + nrow * (PITCH * 2) + ncol * 2);
            #pragma unroll
            for (int mi = 0; mi < 2; mi++)
                #pragma unroll
                for (int j = 0; j < 2; j++)
                    mma_bf16(acc[mi][j], ah[mi], &bb[j * 2]);
        }
    };

    #define LOADG(k0, A0, A1, BH, BL)                              \
        do {                                                       \
            A0 = __ldg((const float4*)(asrc + (k0)));              \
            A1 = __ldg((const float4*)(asrc + (k0) + 4));          \
            BH = *(const uint4*)(bh_src + (k0));                   \
            BL = *(const uint4*)(bl_src + (k0));                   \
        } while (0)

    #define STSREG(nb, A0, A1, BH, BL)                             \
        do {                                                       \
            uint4 hh, ll;                                          \
            split2(A0.x, A0.y, hh.x, ll.x);                        \
            split2(A0.z, A0.w, hh.y, ll.y);                        \
            split2(A1.x, A1.y, hh.z, ll.z);                        \
            split2(A1.z, A1.w, hh.w, ll.w);                        \
            *(uint4*)((nb) + foff)              = hh;              \
            *(uint4*)((nb) + TILE_T + foff)     = ll;              \
            *(uint4*)((nb) + 2 * TILE_T + foff) = BH;              \
            *(uint4*)((nb) + 3 * TILE_T + foff) = BL;              \
        } while (0)

    // ---- prologue: chunk 0 -> smem buf0; chunk 1 -> regs buf1 ----
    LOADG(0, a0_0, a1_0, bh_0, bl_0);
    STSREG(dsm, a0_0, a1_0, bh_0, bl_0);
    LOADG(KC, a0_1, a1_1, bh_1, bl_1);
    __syncthreads();

    for (int c = 0; c < NCHUNK; c += 2) {
        // even step: compute buf0 (chunk c); prefetch c+2 into regs _0;
        // STS regs _1 (chunk c+1) -> buf1
        if (c + 2 < NCHUNK) LOADG((c + 2) * KC, a0_0, a1_0, bh_0, bl_0);
        compute(dyn);
        STSREG(dsm + BUF_B, a0_1, a1_1, bh_1, bl_1);
        __syncthreads();

        // odd step: compute buf1 (chunk c+1); prefetch c+3 into regs _1;
        // STS regs _0 (chunk c+2) -> buf0
        if (c + 3 < NCHUNK) LOADG((c + 3) * KC, a0_1, a1_1, bh_1, bl_1);
        compute(dyn + BUF_B);
        if (c + 2 < NCHUNK) STSREG(dsm, a0_0, a1_0, bh_0, bl_0);
        __syncthreads();
    }
    #undef LOADG
    #undef STSREG

    // =========== fused attention epilogue ===========
    float* att = (float*)dsm;   // att[64][ATT_STRIDE]

    #pragma unroll
    for (int rr = 0; rr < 8; rr++) {
        const int row = wid * 8 + rr;
        const int act = action[(size_t)(rowBase + row) * ADIM + lane];
        float s = g_s_table[act];
        float m = s;
        #pragma unroll
        for (int o = 16; o > 0; o >>= 1)
            m = fmaxf(m, __shfl_xor_sync(0xffffffffu, m, o));
        float p = __expf(s - m);
        float sum = p;
        #pragma unroll
        for (int o = 16; o > 0; o >>= 1)
            sum += __shfl_xor_sync(0xffffffffu, sum, o);
        const float wgt = p / sum;

        float a0 = 0.f, a1 = 0.f;
        #pragma unroll 4
        for (int a = 0; a < 32; a++) {
            const int id  = __shfl_sync(0xffffffffu, act, a);
            const float wa = __shfl_sync(0xffffffffu, wgt, a);
            const float2 t2 = *(const float2*)&g_T2[(size_t)id * ODIM + 2 * lane];
            a0 = fmaf(wa, t2.x, a0);
            a1 = fmaf(wa, t2.y, a1);
        }
        *(float2*)&att[row * ATT_STRIDE + 2 * lane] = make_float2(a0, a1);
    }
    __syncthreads();

    // ---- bias + att + store ----
    const int cbase = warp_n * 16 + (lane & 3) * 2;
    float2 bias[2];
    #pragma unroll
    for (int j = 0; j < 2; j++)
        bias[j] = *(const float2*)&g_bias[cbase + j * 8];

    #pragma unroll
    for (int mi = 0; mi < 2; mi++) {
        const int lr0 = warp_m * 32 + mi * 16 + (lane >> 2);
        const size_t r0 = rowBase + lr0;
        #pragma unroll
        for (int j = 0; j < 2; j++) {
            const int col = cbase + j * 8;
            const float2 at0 = *(const float2*)&att[lr0 * ATT_STRIDE + col];
            const float2 at1 = *(const float2*)&att[(lr0 + 8) * ATT_STRIDE + col];
            float2 lo = make_float2(acc[mi][j][0] + bias[j].x + at0.x,
                                    acc[mi][j][1] + bias[j].y + at0.y);
            float2 hi = make_float2(acc[mi][j][2] + bias[j].x + at1.x,
                                    acc[mi][j][3] + bias[j].y + at1.y);
            *(float2*)&out[r0 * ODIM + col]       = lo;
            *(float2*)&out[(r0 + 8) * ODIM + col] = hi;
        }
    }
}

// ---------------------------------------------------------------------------
extern "C" void kernel_launch(void* const* d_in, const int* in_sizes, int n_in,
                              void* d_out, int out_size)
{
    const float* state   = (const float*)d_in[0];
    const int*   action  = (const int*)  d_in[1];
    const float* W_state = (const float*)d_in[2];
    const float* b_state = (const float*)d_in[3];
    const float* table   = (const float*)d_in[4];
    const float* W_att   = (const float*)d_in[5];
    const float* b_att   = (const float*)d_in[6];
    const float* W_out   = (const float*)d_in[7];
    const float* b_out   = (const float*)d_in[8];
    float* out = (float*)d_out;

    cudaFuncSetAttribute(gemm_fused_kernel,
                         cudaFuncAttributeMaxDynamicSharedMemorySize, DSMEM);

    prep_all_kernel<<<PW_BLOCKS + P2_BLOCKS, 256>>>(
        W_state, W_out, b_state, b_out, table, W_att, b_att);
    gemm_fused_kernel<<<NB / 64, 256, DSMEM>>>(state, action, out);
}